// round 9
// baseline (speedup 1.0000x reference)
#include <cuda_runtime.h>
#include <cstdint>

// DVBundle: deferred-update TMA-ring persistent kernel.
//
// Key idea: DRAM reads (row n, via cp.async.bulk ring) and DRAM writes
// (row n-1 update) are INTERLEAVED in one loop so the HBM bus always has
// work queued; the reduce seam no longer exposes bus idle time. The
// previous row's original w is re-fetched with LDG from global — an L2
// hit, since TMA pulled it through L2 one iteration (~38MB of churn) ago.
//
// w [4096, 8192, 4] f32 = 8192 float4/row = 4 tiles x 32KB.
// x: 8 float4 per thread in registers. Output: [v|r|w_new].
// Grid = 148 persistent CTAs, 1024 threads, 6-slot ring (192KB).
// ONE __syncthreads per iteration: proves slot consumption (pass-A LDS done)
// AND publishes reduce partials; tid0 then issues 4 refills, which stay in
// flight through the reduce and the next iteration's interleave.

#define NI        8192
#define THREADS   1024
#define GRID      148
#define TILE_F4   2048               // 32KB tile
#define TILE_B    32768
#define NBUF      6

#define OFF_RING  0                              // 6 * 32768 = 196608
#define OFF_RED   (NBUF * TILE_B)                // 33*16 = 528
#define OFF_MBAR  (OFF_RED + 33 * 16)
#define SMEM_B    (OFF_MBAR + NBUF * 8)

__device__ __forceinline__ void mbar_wait_acq(uint32_t mbar, uint32_t parity)
{
    uint32_t done;
    asm volatile(
        "{\n\t.reg .pred p;\n\t"
        "mbarrier.try_wait.parity.acquire.cta.shared::cta.b64 p, [%1], %2;\n\t"
        "selp.b32 %0, 1, 0, p;\n\t}"
        : "=r"(done) : "r"(mbar), "r"(parity) : "memory");
    if (!done) {
        asm volatile(
            "{\n\t.reg .pred P1;\n\t"
            "WL_%=:\n\t"
            "mbarrier.try_wait.parity.acquire.cta.shared::cta.b64 P1, [%0], %1, 0x989680;\n\t"
            "@P1 bra.uni WD_%=;\n\t"
            "bra.uni WL_%=;\n\t"
            "WD_%=:\n\t}"
            :: "r"(mbar), "r"(parity) : "memory");
    }
}

// Issue TMA load of tile-stream index s into ring slot (s % 6).
__device__ __forceinline__ void issue_tile(int s, int ntiles, int bid,
                                           const float4* __restrict__ w,
                                           uint32_t smem_base, uint32_t mbar_base)
{
    if (s < ntiles) {
        const int      b  = s % NBUF;
        const uint32_t mb = mbar_base + 8u * b;
        asm volatile("mbarrier.arrive.expect_tx.shared.b64 _, [%0], %1;"
                     :: "r"(mb), "r"((uint32_t)TILE_B) : "memory");
        const void* src = (const void*)(w + (size_t)(bid + (s >> 2) * GRID) * NI
                                          + (size_t)(s & 3) * TILE_F4);
        asm volatile(
            "cp.async.bulk.shared::cluster.global.mbarrier::complete_tx::bytes "
            "[%0], [%1], %2, [%3];"
            :: "r"(smem_base + (uint32_t)(b * TILE_B)),
               "l"(src), "r"((uint32_t)TILE_B), "r"(mb) : "memory");
    }
}

__global__ __launch_bounds__(THREADS, 1)
void dvbundle_defer(const float4* __restrict__ w,
                    const float4* __restrict__ x,
                    const float*  __restrict__ v,
                    const float*  __restrict__ r,
                    float*        __restrict__ v_out,
                    float*        __restrict__ r_out,
                    float4*       __restrict__ w_out,
                    int n_neurons)
{
    extern __shared__ char smem[];
    float4* ring = (float4*)(smem + OFF_RING);
    float4* red  = (float4*)(smem + OFF_RED);

    const int tid  = threadIdx.x;
    const int warp = tid >> 5;
    const int lane = tid & 31;
    const int bid  = blockIdx.x;

    const uint32_t smem_base = (uint32_t)__cvta_generic_to_shared(smem);
    const uint32_t mbar_base = smem_base + OFF_MBAR;

    // ---- x slice: permanent registers (8 float4 = 32 regs) ----
    float4 xr[8];
#pragma unroll
    for (int j = 0; j < 8; ++j)
        xr[j] = x[tid + j * THREADS];

    if (tid == 0) {
#pragma unroll
        for (int b = 0; b < NBUF; ++b)
            asm volatile("mbarrier.init.shared.b64 [%0], %1;"
                         :: "r"(mbar_base + 8u * b), "r"(1u) : "memory");
    }
    __syncthreads();

    const int niters = (n_neurons - bid + GRID - 1) / GRID;
    const int ntiles = 4 * niters;

    if (tid == 0) {
#pragma unroll
        for (int s = 0; s < NBUF; ++s)
            issue_tile(s, ntiles, bid, w, smem_base, mbar_base);
    }

    // Carried state: previous row's I and update scalar.
    float Ixp = 0.f, Iyp = 0.f, Izp = 0.f, Iwp = 0.f, regp = 0.f;

    for (int it = 0; it <= niters; ++it) {
        const int  n       = bid + it * GRID;
        const int  p       = n - GRID;            // previous row (write target)
        const bool doRead  = (it < niters);
        const bool doWrite = (it > 0);
        const int  s0      = 4 * it;

        const float vn = doRead ? v[n] : 0.f;
        const float rn = doRead ? r[n] : 0.f;

        const float4* pin  = w     + (size_t)(doWrite ? p : 0) * NI;  // L2-hot
        float4*       pout = w_out + (size_t)(doWrite ? p : 0) * NI;

        // ---- Interleaved loop: read row n (TMA ring) + write row p ----
        float ax = 0.f, ay = 0.f, az = 0.f, aw = 0.f;
#pragma unroll
        for (int q = 0; q < 4; ++q) {
            // LDG previous row's tile early (L2 hit), latency hidden.
            float4 pw0, pw1;
            if (doWrite) {
                pw0 = pin[q * TILE_F4 + tid];
                pw1 = pin[q * TILE_F4 + THREADS + tid];
            }

            if (doRead) {
                const int s = s0 + q;
                const int b = s % NBUF;
                mbar_wait_acq(mbar_base + 8u * b, (uint32_t)(s / NBUF) & 1u);
                const float4* wb = ring + b * TILE_F4;
                const float4 w0 = wb[tid];
                const float4 w1 = wb[tid + THREADS];
                ax = fmaf(w0.x, xr[2 * q].x, ax); ax = fmaf(w1.x, xr[2 * q + 1].x, ax);
                ay = fmaf(w0.y, xr[2 * q].y, ay); ay = fmaf(w1.y, xr[2 * q + 1].y, ay);
                az = fmaf(w0.z, xr[2 * q].z, az); az = fmaf(w1.z, xr[2 * q + 1].z, az);
                aw = fmaf(w0.w, xr[2 * q].w, aw); aw = fmaf(w1.w, xr[2 * q + 1].w, aw);
            }

            if (doWrite) {
                float4 o0, o1;
                o0.x = fmaf(regp, fmaf(-pw0.x, Ixp, 0.5f * xr[2 * q].x), pw0.x);
                o0.y = fmaf(regp, fmaf(-pw0.y, Iyp, 0.5f * xr[2 * q].y), pw0.y);
                o0.z = fmaf(regp, fmaf(-pw0.z, Izp, 0.5f * xr[2 * q].z), pw0.z);
                o0.w = fmaf(regp, fmaf(-pw0.w, Iwp, 0.5f * xr[2 * q].w), pw0.w);
                o1.x = fmaf(regp, fmaf(-pw1.x, Ixp, 0.5f * xr[2 * q + 1].x), pw1.x);
                o1.y = fmaf(regp, fmaf(-pw1.y, Iyp, 0.5f * xr[2 * q + 1].y), pw1.y);
                o1.z = fmaf(regp, fmaf(-pw1.z, Izp, 0.5f * xr[2 * q + 1].z), pw1.z);
                o1.w = fmaf(regp, fmaf(-pw1.w, Iwp, 0.5f * xr[2 * q + 1].w), pw1.w);
                pout[q * TILE_F4 + tid]           = o0;
                pout[q * TILE_F4 + THREADS + tid] = o1;
            }
        }

        if (!doRead) break;          // write-only epilogue done

        // ---- Warp reduce, publish partials; ONE barrier; refill 4 slots ----
#pragma unroll
        for (int o = 16; o > 0; o >>= 1) {
            ax += __shfl_xor_sync(0xffffffffu, ax, o);
            ay += __shfl_xor_sync(0xffffffffu, ay, o);
            az += __shfl_xor_sync(0xffffffffu, az, o);
            aw += __shfl_xor_sync(0xffffffffu, aw, o);
        }
        if (lane == 0) red[warp] = make_float4(ax, ay, az, aw);
        __syncthreads();             // proves LDS of slots s0..s0+3 done too

        if (tid == 0) {
            issue_tile(s0 + 6, ntiles, bid, w, smem_base, mbar_base);
            issue_tile(s0 + 7, ntiles, bid, w, smem_base, mbar_base);
            issue_tile(s0 + 8, ntiles, bid, w, smem_base, mbar_base);
            issue_tile(s0 + 9, ntiles, bid, w, smem_base, mbar_base);
        }

        float4 t = red[lane];
        float Ix = t.x, Iy = t.y, Iz = t.z, Iw = t.w;
#pragma unroll
        for (int o = 16; o > 0; o >>= 1) {
            Ix += __shfl_xor_sync(0xffffffffu, Ix, o);
            Iy += __shfl_xor_sync(0xffffffffu, Iy, o);
            Iz += __shfl_xor_sync(0xffffffffu, Iz, o);
            Iw += __shfl_xor_sync(0xffffffffu, Iw, o);
        }

        // ---- Scalar neuron update for row n; carry I/reg to next iter ----
        const float S    = Ix - Iy + Iz - Iw;
        const float dv   = (S - vn) * 0.05f;            // DT/TAU_V
        const float th   = tanhf(vn);
        const float actd = (vn > 0.f) ? (1.f - th * th) : 0.f;

        if (tid == 0) {
            v_out[n] = vn + dv;
            r_out[n] = (vn > 0.f) ? th : 0.f;
        }

        Ixp = Ix; Iyp = Iy; Izp = Iz; Iwp = Iw;
        regp = rn * actd * dv * 0.02f;                  // / TAU_W
    }
}

extern "C" void kernel_launch(void* const* d_in, const int* in_sizes, int n_in,
                              void* d_out, int out_size)
{
    const float4* w = (const float4*)d_in[0];
    const float4* x = (const float4*)d_in[1];
    const float*  v = (const float*)d_in[2];
    const float*  r = (const float*)d_in[3];

    const int N = in_sizes[2];                 // 4096 neurons

    float*  out   = (float*)d_out;
    float*  v_out = out;
    float*  r_out = out + N;
    float4* w_out = (float4*)(out + 2 * (size_t)N);

    cudaFuncSetAttribute(dvbundle_defer,
                         cudaFuncAttributeMaxDynamicSharedMemorySize,
                         SMEM_B);

    dvbundle_defer<<<GRID, THREADS, SMEM_B>>>(w, x, v, r, v_out, r_out, w_out, N);
}

// round 10
// speedup vs baseline: 1.0607x; 1.0607x over previous
#include <cuda_runtime.h>
#include <cuda_fp16.h>
#include <cstdint>

// DVBundle: one-barrier TMA-ring persistent kernel, full register residency.
//
// w [4096, 8192, 4] f32 = 8192 float4/row = 4 tiles x 32KB.
// x [8192,4]: per-thread slice held in registers as fp16 (16 half2 regs).
// Output: [v_new (N) | r_new (N) | w_new (N*8192*4)]
//
// Grid = 148 persistent CTAs, 1024 threads, 7-deep smem ring (224KB).
// Pass 1: per-tile mbar wait + LDS -> stash w in regs + FMA (no barriers).
// ONE __syncthreads (reduce publish; also proves all 4 slots consumed).
// tid0 then issues the ENTIRE next row (4 tiles); lookahead = 7 tiles, so
// TMA streams continuously through reduce, pass 2 (pure regs + STG), and
// the next pass 1. smem traffic = 256KB/iter (TMA-in + pass-1 LDS only).

#define NI        8192
#define THREADS   1024
#define GRID      148
#define TILE_F4   2048               // 32KB tile
#define TILE_B    32768
#define NBUF      7

#define OFF_RING  0                              // 7 * 32768 = 229376
#define OFF_RED   (NBUF * TILE_B)                // 33*16 = 528
#define OFF_MBAR  (OFF_RED + 33 * 16)            // 229904
#define SMEM_B    (OFF_MBAR + NBUF * 8)          // 229960

__device__ __forceinline__ void mbar_wait_acq(uint32_t mbar, uint32_t parity)
{
    uint32_t done;
    asm volatile(
        "{\n\t.reg .pred p;\n\t"
        "mbarrier.try_wait.parity.acquire.cta.shared::cta.b64 p, [%1], %2;\n\t"
        "selp.b32 %0, 1, 0, p;\n\t}"
        : "=r"(done) : "r"(mbar), "r"(parity) : "memory");
    if (!done) {
        asm volatile(
            "{\n\t.reg .pred P1;\n\t"
            "WL_%=:\n\t"
            "mbarrier.try_wait.parity.acquire.cta.shared::cta.b64 P1, [%0], %1, 0x989680;\n\t"
            "@P1 bra.uni WD_%=;\n\t"
            "bra.uni WL_%=;\n\t"
            "WD_%=:\n\t}"
            :: "r"(mbar), "r"(parity) : "memory");
    }
}

// Issue TMA load of tile-stream index s into ring slot (s % 7).
__device__ __forceinline__ void issue_tile(int s, int ntiles, int bid,
                                           const float4* __restrict__ w,
                                           uint32_t smem_base, uint32_t mbar_base)
{
    if (s < ntiles) {
        const int      b  = s % NBUF;
        const uint32_t mb = mbar_base + 8u * b;
        asm volatile("mbarrier.arrive.expect_tx.shared.b64 _, [%0], %1;"
                     :: "r"(mb), "r"((uint32_t)TILE_B) : "memory");
        const void* src = (const void*)(w + (size_t)(bid + (s >> 2) * GRID) * NI
                                          + (size_t)(s & 3) * TILE_F4);
        asm volatile(
            "cp.async.bulk.shared::cluster.global.mbarrier::complete_tx::bytes "
            "[%0], [%1], %2, [%3];"
            :: "r"(smem_base + (uint32_t)(b * TILE_B)),
               "l"(src), "r"((uint32_t)TILE_B), "r"(mb) : "memory");
    }
}

__global__ __launch_bounds__(THREADS, 1)
void dvbundle_1bar(const float4* __restrict__ w,
                   const float4* __restrict__ x,
                   const float*  __restrict__ v,
                   const float*  __restrict__ r,
                   float*        __restrict__ v_out,
                   float*        __restrict__ r_out,
                   float4*       __restrict__ w_out,
                   int n_neurons)
{
    extern __shared__ char smem[];
    float4* ring = (float4*)(smem + OFF_RING);
    float4* red  = (float4*)(smem + OFF_RED);

    const int tid  = threadIdx.x;
    const int warp = tid >> 5;
    const int lane = tid & 31;
    const int bid  = blockIdx.x;

    const uint32_t smem_base = (uint32_t)__cvta_generic_to_shared(smem);
    const uint32_t mbar_base = smem_base + OFF_MBAR;

    // ---- x slice in registers as fp16: 8 float4 -> 16 half2 ----
    __half2 xh[16];
#pragma unroll
    for (int j = 0; j < 8; ++j) {
        const float4 t = x[tid + j * THREADS];
        xh[2 * j]     = __floats2half2_rn(t.x, t.y);
        xh[2 * j + 1] = __floats2half2_rn(t.z, t.w);
    }

    if (tid == 0) {
#pragma unroll
        for (int b = 0; b < NBUF; ++b)
            asm volatile("mbarrier.init.shared.b64 [%0], %1;"
                         :: "r"(mbar_base + 8u * b), "r"(1u) : "memory");
    }
    __syncthreads();

    const int niters = (n_neurons - bid + GRID - 1) / GRID;
    const int ntiles = 4 * niters;

    if (tid == 0) {
#pragma unroll
        for (int s = 0; s < NBUF; ++s)
            issue_tile(s, ntiles, bid, w, smem_base, mbar_base);
    }

    int n = bid;
    for (int it = 0; it < niters; ++it, n += GRID) {
        const float vn = v[n];
        const float rn = r[n];
        const int   s0 = 4 * it;

        // ---- Pass 1: mbar wait + LDS -> reg stash + FMA (no barriers) ----
        float4 wv[8];
        float ax = 0.f, ay = 0.f, az = 0.f, aw = 0.f;
#pragma unroll
        for (int q = 0; q < 4; ++q) {
            const int s = s0 + q;
            const int b = s % NBUF;
            mbar_wait_acq(mbar_base + 8u * b, (uint32_t)(s / NBUF) & 1u);

            const float4* wb = ring + b * TILE_F4;
            const float4 w0 = wb[tid];
            const float4 w1 = wb[tid + THREADS];
            wv[2 * q]     = w0;
            wv[2 * q + 1] = w1;
            const float2 x0a = __half22float2(xh[4 * q]);
            const float2 x0b = __half22float2(xh[4 * q + 1]);
            const float2 x1a = __half22float2(xh[4 * q + 2]);
            const float2 x1b = __half22float2(xh[4 * q + 3]);
            ax = fmaf(w0.x, x0a.x, ax); ax = fmaf(w1.x, x1a.x, ax);
            ay = fmaf(w0.y, x0a.y, ay); ay = fmaf(w1.y, x1a.y, ay);
            az = fmaf(w0.z, x0b.x, az); az = fmaf(w1.z, x1b.x, az);
            aw = fmaf(w0.w, x0b.y, aw); aw = fmaf(w1.w, x1b.y, aw);
        }

        // ---- Reduce: shfl -> partials -> THE barrier -> refill + reduce ----
#pragma unroll
        for (int o = 16; o > 0; o >>= 1) {
            ax += __shfl_xor_sync(0xffffffffu, ax, o);
            ay += __shfl_xor_sync(0xffffffffu, ay, o);
            az += __shfl_xor_sync(0xffffffffu, az, o);
            aw += __shfl_xor_sync(0xffffffffu, aw, o);
        }
        if (lane == 0) red[warp] = make_float4(ax, ay, az, aw);
        __syncthreads();       // publishes partials AND proves slots s0..s0+3 free

        if (tid == 0) {        // refill: entire next row, ASAP
            issue_tile(s0 + NBUF,     ntiles, bid, w, smem_base, mbar_base);
            issue_tile(s0 + NBUF + 1, ntiles, bid, w, smem_base, mbar_base);
            issue_tile(s0 + NBUF + 2, ntiles, bid, w, smem_base, mbar_base);
            issue_tile(s0 + NBUF + 3, ntiles, bid, w, smem_base, mbar_base);
        }

        float4 t = red[lane];
        float Ix = t.x, Iy = t.y, Iz = t.z, Iw = t.w;
#pragma unroll
        for (int o = 16; o > 0; o >>= 1) {
            Ix += __shfl_xor_sync(0xffffffffu, Ix, o);
            Iy += __shfl_xor_sync(0xffffffffu, Iy, o);
            Iz += __shfl_xor_sync(0xffffffffu, Iz, o);
            Iw += __shfl_xor_sync(0xffffffffu, Iw, o);
        }

        // ---- Scalar neuron update ----
        const float S    = Ix - Iy + Iz - Iw;
        const float dv   = (S - vn) * 0.05f;            // DT/TAU_V
        const float th   = tanhf(vn);
        const float actd = (vn > 0.f) ? (1.f - th * th) : 0.f;
        const float reg  = rn * actd * dv * 0.02f;      // / TAU_W

        if (tid == 0) {
            v_out[n] = vn + dv;
            r_out[n] = (vn > 0.f) ? th : 0.f;
        }

        // ---- Pass 2: pure regs -> STG (no smem) ----
        float4* wdst = w_out + (size_t)n * NI;
#pragma unroll
        for (int q = 0; q < 4; ++q) {
#pragma unroll
            for (int h = 0; h < 2; ++h) {
                const float4 wj  = wv[2 * q + h];
                const float2 xa  = __half22float2(xh[4 * q + 2 * h]);
                const float2 xb  = __half22float2(xh[4 * q + 2 * h + 1]);
                float4 o;
                o.x = fmaf(reg, fmaf(-wj.x, Ix, 0.5f * xa.x), wj.x);
                o.y = fmaf(reg, fmaf(-wj.y, Iy, 0.5f * xa.y), wj.y);
                o.z = fmaf(reg, fmaf(-wj.z, Iz, 0.5f * xb.x), wj.z);
                o.w = fmaf(reg, fmaf(-wj.w, Iw, 0.5f * xb.y), wj.w);
                wdst[q * TILE_F4 + h * THREADS + tid] = o;
            }
        }
    }
}

extern "C" void kernel_launch(void* const* d_in, const int* in_sizes, int n_in,
                              void* d_out, int out_size)
{
    const float4* w = (const float4*)d_in[0];
    const float4* x = (const float4*)d_in[1];
    const float*  v = (const float*)d_in[2];
    const float*  r = (const float*)d_in[3];

    const int N = in_sizes[2];                 // 4096 neurons

    float*  out   = (float*)d_out;
    float*  v_out = out;
    float*  r_out = out + N;
    float4* w_out = (float4*)(out + 2 * (size_t)N);

    cudaFuncSetAttribute(dvbundle_1bar,
                         cudaFuncAttributeMaxDynamicSharedMemorySize,
                         SMEM_B);

    dvbundle_1bar<<<GRID, THREADS, SMEM_B>>>(w, x, v, r, v_out, r_out, w_out, N);
}

// round 11
// speedup vs baseline: 1.1630x; 1.0964x over previous
#include <cuda_runtime.h>
#include <cstdint>

// DVBundle: iteration-pipelined TMA-ring persistent kernel.
//
// Software pipeline: the STG of row n-1 (w held in the wv[8] register stash
// from its own pass 1 -- never refetched) is interleaved tile-by-tile with
// the TMA-fed read+FMA of row n. DRAM read and write streams are mixed in
// every loop body (R9 showed the bus does 6.5TB/s on mixed streams), while
// total traffic stays at the mandatory 1.07GB (R9's refetch flaw removed).
//
// w [4096, 8192, 4] f32 = 8192 float4/row = 4 tiles x 32KB.
// x [8192,4] = 128KB cached in smem once. Output: [v|r|w_new].
// Grid = 148 persistent CTAs, 1024 threads, 3-slot ring (96KB).
// Per tile: LDS x, STG prev tile, mbar wait, LDS w -> stash + FMA,
// __syncthreads + refill (R4's proven slot protocol; tile 3's refill rides
// the reduce barrier). One extra write-only epilogue iteration.

#define NI        8192
#define THREADS   1024
#define GRID      148
#define TILE_F4   2048               // 32KB tile
#define TILE_B    32768
#define NBUF      3

#define OFF_X     0                              // 8192*16 = 131072
#define OFF_RING  131072                         // 3*32768 = 98304
#define OFF_RED   (OFF_RING + NBUF * TILE_B)     // 229376, 33*16 = 528
#define OFF_MBAR  (OFF_RED + 33 * 16)            // 229904
#define SMEM_B    (OFF_MBAR + NBUF * 8)          // 229928

__device__ __forceinline__ void mbar_wait_acq(uint32_t mbar, uint32_t parity)
{
    uint32_t done;
    asm volatile(
        "{\n\t.reg .pred p;\n\t"
        "mbarrier.try_wait.parity.acquire.cta.shared::cta.b64 p, [%1], %2;\n\t"
        "selp.b32 %0, 1, 0, p;\n\t}"
        : "=r"(done) : "r"(mbar), "r"(parity) : "memory");
    if (!done) {
        asm volatile(
            "{\n\t.reg .pred P1;\n\t"
            "WL_%=:\n\t"
            "mbarrier.try_wait.parity.acquire.cta.shared::cta.b64 P1, [%0], %1, 0x989680;\n\t"
            "@P1 bra.uni WD_%=;\n\t"
            "bra.uni WL_%=;\n\t"
            "WD_%=:\n\t}"
            :: "r"(mbar), "r"(parity) : "memory");
    }
}

// Issue TMA load of tile-stream index s into ring slot (s % 3).
__device__ __forceinline__ void issue_tile(int s, int ntiles, int bid,
                                           const float4* __restrict__ w,
                                           uint32_t smem_base, uint32_t mbar_base)
{
    if (s < ntiles) {
        const int      b  = s % NBUF;
        const uint32_t mb = mbar_base + 8u * b;
        asm volatile("mbarrier.arrive.expect_tx.shared.b64 _, [%0], %1;"
                     :: "r"(mb), "r"((uint32_t)TILE_B) : "memory");
        const void* src = (const void*)(w + (size_t)(bid + (s >> 2) * GRID) * NI
                                          + (size_t)(s & 3) * TILE_F4);
        asm volatile(
            "cp.async.bulk.shared::cluster.global.mbarrier::complete_tx::bytes "
            "[%0], [%1], %2, [%3];"
            :: "r"(smem_base + (uint32_t)OFF_RING + (uint32_t)(b * TILE_B)),
               "l"(src), "r"((uint32_t)TILE_B), "r"(mb) : "memory");
    }
}

__global__ __launch_bounds__(THREADS, 1)
void dvbundle_pipe(const float4* __restrict__ w,
                   const float4* __restrict__ x,
                   const float*  __restrict__ v,
                   const float*  __restrict__ r,
                   float*        __restrict__ v_out,
                   float*        __restrict__ r_out,
                   float4*       __restrict__ w_out,
                   int n_neurons)
{
    extern __shared__ char smem[];
    float4* xs   = (float4*)(smem + OFF_X);
    float4* ring = (float4*)(smem + OFF_RING);
    float4* red  = (float4*)(smem + OFF_RED);

    const int tid  = threadIdx.x;
    const int warp = tid >> 5;
    const int lane = tid & 31;
    const int bid  = blockIdx.x;

    const uint32_t smem_base = (uint32_t)__cvta_generic_to_shared(smem);
    const uint32_t mbar_base = smem_base + OFF_MBAR;

    // ---- Prologue: x -> smem, init mbars, prime the ring ----
#pragma unroll
    for (int j = 0; j < 8; ++j)
        xs[tid + j * THREADS] = x[tid + j * THREADS];

    if (tid == 0) {
#pragma unroll
        for (int b = 0; b < NBUF; ++b)
            asm volatile("mbarrier.init.shared.b64 [%0], %1;"
                         :: "r"(mbar_base + 8u * b), "r"(1u) : "memory");
    }
    __syncthreads();

    const int niters = (n_neurons - bid + GRID - 1) / GRID;
    const int ntiles = 4 * niters;

    if (tid == 0) {
        issue_tile(0, ntiles, bid, w, smem_base, mbar_base);
        issue_tile(1, ntiles, bid, w, smem_base, mbar_base);
        issue_tile(2, ntiles, bid, w, smem_base, mbar_base);
    }

    // Pipeline state: previous row's w (registers), I and update scalar.
    float4 wv[8];
    float  Ixp = 0.f, Iyp = 0.f, Izp = 0.f, Iwp = 0.f, regp = 0.f;

    for (int it = 0; it <= niters; ++it) {
        const int  n       = bid + it * GRID;
        const bool doRead  = (it < niters);
        const bool doWrite = (it > 0);
        const int  s0      = 4 * it;

        const float vn = doRead ? v[n] : 0.f;
        const float rn = doRead ? r[n] : 0.f;

        float4* pout = w_out + (size_t)(doWrite ? (n - GRID) : 0) * NI;

        // ---- Merged loop: STG row n-1 tile q, then read+FMA row n tile q ----
        float ax = 0.f, ay = 0.f, az = 0.f, aw = 0.f;
#pragma unroll
        for (int q = 0; q < 4; ++q) {
            const float4 x0 = xs[q * TILE_F4 + tid];
            const float4 x1 = xs[q * TILE_F4 + THREADS + tid];

            if (doWrite) {            // write prev tile q from the stash
                const float4 a = wv[2 * q];
                const float4 c = wv[2 * q + 1];
                float4 o0, o1;
                o0.x = fmaf(regp, fmaf(-a.x, Ixp, 0.5f * x0.x), a.x);
                o0.y = fmaf(regp, fmaf(-a.y, Iyp, 0.5f * x0.y), a.y);
                o0.z = fmaf(regp, fmaf(-a.z, Izp, 0.5f * x0.z), a.z);
                o0.w = fmaf(regp, fmaf(-a.w, Iwp, 0.5f * x0.w), a.w);
                o1.x = fmaf(regp, fmaf(-c.x, Ixp, 0.5f * x1.x), c.x);
                o1.y = fmaf(regp, fmaf(-c.y, Iyp, 0.5f * x1.y), c.y);
                o1.z = fmaf(regp, fmaf(-c.z, Izp, 0.5f * x1.z), c.z);
                o1.w = fmaf(regp, fmaf(-c.w, Iwp, 0.5f * x1.w), c.w);
                pout[q * TILE_F4 + tid]           = o0;
                pout[q * TILE_F4 + THREADS + tid] = o1;
            }

            if (doRead) {             // read row n tile q into the freed stash
                const int s = s0 + q;
                const int b = s % NBUF;
                mbar_wait_acq(mbar_base + 8u * b, (uint32_t)(s / NBUF) & 1u);

                const float4* wb = ring + b * TILE_F4;
                const float4 w0 = wb[tid];
                const float4 w1 = wb[tid + THREADS];
                wv[2 * q]     = w0;
                wv[2 * q + 1] = w1;
                ax = fmaf(w0.x, x0.x, ax); ax = fmaf(w1.x, x1.x, ax);
                ay = fmaf(w0.y, x0.y, ay); ay = fmaf(w1.y, x1.y, ay);
                az = fmaf(w0.z, x0.z, az); az = fmaf(w1.z, x1.z, az);
                aw = fmaf(w0.w, x0.w, aw); aw = fmaf(w1.w, x1.w, aw);

                if (q < 3) {
                    __syncthreads();           // slot b consumed by all warps
                    if (tid == 0)
                        issue_tile(s + NBUF, ntiles, bid, w, smem_base, mbar_base);
                }
            }
        }

        if (!doRead) break;           // write-only epilogue done

        // ---- Reduce (barrier also proves tile 3's slot consumed) ----
#pragma unroll
        for (int o = 16; o > 0; o >>= 1) {
            ax += __shfl_xor_sync(0xffffffffu, ax, o);
            ay += __shfl_xor_sync(0xffffffffu, ay, o);
            az += __shfl_xor_sync(0xffffffffu, az, o);
            aw += __shfl_xor_sync(0xffffffffu, aw, o);
        }
        if (lane == 0) red[warp] = make_float4(ax, ay, az, aw);
        __syncthreads();

        if (tid == 0)
            issue_tile(s0 + 3 + NBUF, ntiles, bid, w, smem_base, mbar_base);

        float4 t = red[lane];
        float Ix = t.x, Iy = t.y, Iz = t.z, Iw = t.w;
#pragma unroll
        for (int o = 16; o > 0; o >>= 1) {
            Ix += __shfl_xor_sync(0xffffffffu, Ix, o);
            Iy += __shfl_xor_sync(0xffffffffu, Iy, o);
            Iz += __shfl_xor_sync(0xffffffffu, Iz, o);
            Iw += __shfl_xor_sync(0xffffffffu, Iw, o);
        }

        // ---- Scalar neuron update; carry to next iteration ----
        const float S    = Ix - Iy + Iz - Iw;
        const float dv   = (S - vn) * 0.05f;            // DT/TAU_V
        const float th   = tanhf(vn);
        const float actd = (vn > 0.f) ? (1.f - th * th) : 0.f;

        if (tid == 0) {
            v_out[n] = vn + dv;
            r_out[n] = (vn > 0.f) ? th : 0.f;
        }

        Ixp = Ix; Iyp = Iy; Izp = Iz; Iwp = Iw;
        regp = rn * actd * dv * 0.02f;                  // / TAU_W
    }
}

extern "C" void kernel_launch(void* const* d_in, const int* in_sizes, int n_in,
                              void* d_out, int out_size)
{
    const float4* w = (const float4*)d_in[0];
    const float4* x = (const float4*)d_in[1];
    const float*  v = (const float*)d_in[2];
    const float*  r = (const float*)d_in[3];

    const int N = in_sizes[2];                 // 4096 neurons

    float*  out   = (float*)d_out;
    float*  v_out = out;
    float*  r_out = out + N;
    float4* w_out = (float4*)(out + 2 * (size_t)N);

    cudaFuncSetAttribute(dvbundle_pipe,
                         cudaFuncAttributeMaxDynamicSharedMemorySize,
                         SMEM_B);

    dvbundle_pipe<<<GRID, THREADS, SMEM_B>>>(w, x, v, r, v_out, r_out, w_out, N);
}

// round 12
// speedup vs baseline: 1.2024x; 1.0339x over previous
#include <cuda_runtime.h>
#include <cstdint>

// DVBundle: iteration-pipelined TMA-ring persistent kernel (3 barriers/iter).
//
// Software pipeline: the STG of row n-1 (w held in the wv[8] register stash
// from its own pass 1 -- never refetched) is interleaved tile-by-tile with
// the TMA-fed read+FMA of row n, so DRAM reads and writes mix continuously.
// Total traffic = mandatory 1.074GB. Refills batched: barrier after tile 0
// (issue s0+3), after tile 2 (issue s0+4, s0+5), and the reduce barrier
// (issue s0+6) -- 3 __syncthreads per iteration instead of 5, with the full
// next row in flight across the reduce + write phase.
//
// w [4096, 8192, 4] f32 = 8192 float4/row = 4 tiles x 32KB.
// x [8192,4] = 128KB cached in smem once. Output: [v|r|w_new].
// Grid = 148 persistent CTAs, 1024 threads, 3-slot ring (96KB).

#define NI        8192
#define THREADS   1024
#define GRID      148
#define TILE_F4   2048               // 32KB tile
#define TILE_B    32768
#define NBUF      3

#define OFF_X     0                              // 8192*16 = 131072
#define OFF_RING  131072                         // 3*32768 = 98304
#define OFF_RED   (OFF_RING + NBUF * TILE_B)     // 229376, 33*16 = 528
#define OFF_MBAR  (OFF_RED + 33 * 16)            // 229904
#define SMEM_B    (OFF_MBAR + NBUF * 8)          // 229928

__device__ __forceinline__ void mbar_wait_acq(uint32_t mbar, uint32_t parity)
{
    uint32_t done;
    asm volatile(
        "{\n\t.reg .pred p;\n\t"
        "mbarrier.try_wait.parity.acquire.cta.shared::cta.b64 p, [%1], %2;\n\t"
        "selp.b32 %0, 1, 0, p;\n\t}"
        : "=r"(done) : "r"(mbar), "r"(parity) : "memory");
    if (!done) {
        asm volatile(
            "{\n\t.reg .pred P1;\n\t"
            "WL_%=:\n\t"
            "mbarrier.try_wait.parity.acquire.cta.shared::cta.b64 P1, [%0], %1, 0x989680;\n\t"
            "@P1 bra.uni WD_%=;\n\t"
            "bra.uni WL_%=;\n\t"
            "WD_%=:\n\t}"
            :: "r"(mbar), "r"(parity) : "memory");
    }
}

// Issue TMA load of tile-stream index s into ring slot (s % 3).
__device__ __forceinline__ void issue_tile(int s, int ntiles, int bid,
                                           const float4* __restrict__ w,
                                           uint32_t smem_base, uint32_t mbar_base)
{
    if (s < ntiles) {
        const int      b  = s % NBUF;
        const uint32_t mb = mbar_base + 8u * b;
        asm volatile("mbarrier.arrive.expect_tx.shared.b64 _, [%0], %1;"
                     :: "r"(mb), "r"((uint32_t)TILE_B) : "memory");
        const void* src = (const void*)(w + (size_t)(bid + (s >> 2) * GRID) * NI
                                          + (size_t)(s & 3) * TILE_F4);
        asm volatile(
            "cp.async.bulk.shared::cluster.global.mbarrier::complete_tx::bytes "
            "[%0], [%1], %2, [%3];"
            :: "r"(smem_base + (uint32_t)OFF_RING + (uint32_t)(b * TILE_B)),
               "l"(src), "r"((uint32_t)TILE_B), "r"(mb) : "memory");
    }
}

__global__ __launch_bounds__(THREADS, 1)
void dvbundle_pipe3(const float4* __restrict__ w,
                    const float4* __restrict__ x,
                    const float*  __restrict__ v,
                    const float*  __restrict__ r,
                    float*        __restrict__ v_out,
                    float*        __restrict__ r_out,
                    float4*       __restrict__ w_out,
                    int n_neurons)
{
    extern __shared__ char smem[];
    float4* xs   = (float4*)(smem + OFF_X);
    float4* ring = (float4*)(smem + OFF_RING);
    float4* red  = (float4*)(smem + OFF_RED);

    const int tid  = threadIdx.x;
    const int warp = tid >> 5;
    const int lane = tid & 31;
    const int bid  = blockIdx.x;

    const uint32_t smem_base = (uint32_t)__cvta_generic_to_shared(smem);
    const uint32_t mbar_base = smem_base + OFF_MBAR;

    // ---- Prologue: x -> smem, init mbars, prime the ring ----
#pragma unroll
    for (int j = 0; j < 8; ++j)
        xs[tid + j * THREADS] = x[tid + j * THREADS];

    if (tid == 0) {
#pragma unroll
        for (int b = 0; b < NBUF; ++b)
            asm volatile("mbarrier.init.shared.b64 [%0], %1;"
                         :: "r"(mbar_base + 8u * b), "r"(1u) : "memory");
    }
    __syncthreads();

    const int niters = (n_neurons - bid + GRID - 1) / GRID;
    const int ntiles = 4 * niters;

    if (tid == 0) {
        issue_tile(0, ntiles, bid, w, smem_base, mbar_base);
        issue_tile(1, ntiles, bid, w, smem_base, mbar_base);
        issue_tile(2, ntiles, bid, w, smem_base, mbar_base);
    }

    // Pipeline state: previous row's w (registers), I and update scalar.
    float4 wv[8];
    float  Ixp = 0.f, Iyp = 0.f, Izp = 0.f, Iwp = 0.f, regp = 0.f;

    for (int it = 0; it <= niters; ++it) {
        const int  n       = bid + it * GRID;
        const bool doRead  = (it < niters);
        const bool doWrite = (it > 0);
        const int  s0      = 4 * it;

        const float vn = doRead ? v[n] : 0.f;
        const float rn = doRead ? r[n] : 0.f;

        float4* pout = w_out + (size_t)(doWrite ? (n - GRID) : 0) * NI;

        // ---- Merged loop: STG row n-1 tile q, then read+FMA row n tile q ----
        float ax = 0.f, ay = 0.f, az = 0.f, aw = 0.f;
#pragma unroll
        for (int q = 0; q < 4; ++q) {
            const float4 x0 = xs[q * TILE_F4 + tid];
            const float4 x1 = xs[q * TILE_F4 + THREADS + tid];

            if (doWrite) {            // write prev tile q from the stash
                const float4 a = wv[2 * q];
                const float4 c = wv[2 * q + 1];
                float4 o0, o1;
                o0.x = fmaf(regp, fmaf(-a.x, Ixp, 0.5f * x0.x), a.x);
                o0.y = fmaf(regp, fmaf(-a.y, Iyp, 0.5f * x0.y), a.y);
                o0.z = fmaf(regp, fmaf(-a.z, Izp, 0.5f * x0.z), a.z);
                o0.w = fmaf(regp, fmaf(-a.w, Iwp, 0.5f * x0.w), a.w);
                o1.x = fmaf(regp, fmaf(-c.x, Ixp, 0.5f * x1.x), c.x);
                o1.y = fmaf(regp, fmaf(-c.y, Iyp, 0.5f * x1.y), c.y);
                o1.z = fmaf(regp, fmaf(-c.z, Izp, 0.5f * x1.z), c.z);
                o1.w = fmaf(regp, fmaf(-c.w, Iwp, 0.5f * x1.w), c.w);
                pout[q * TILE_F4 + tid]           = o0;
                pout[q * TILE_F4 + THREADS + tid] = o1;
            }

            if (doRead) {             // read row n tile q into the freed stash
                const int s = s0 + q;
                const int b = s % NBUF;
                mbar_wait_acq(mbar_base + 8u * b, (uint32_t)(s / NBUF) & 1u);

                const float4* wb = ring + b * TILE_F4;
                const float4 w0 = wb[tid];
                const float4 w1 = wb[tid + THREADS];
                wv[2 * q]     = w0;
                wv[2 * q + 1] = w1;
                ax = fmaf(w0.x, x0.x, ax); ax = fmaf(w1.x, x1.x, ax);
                ay = fmaf(w0.y, x0.y, ay); ay = fmaf(w1.y, x1.y, ay);
                az = fmaf(w0.z, x0.z, az); az = fmaf(w1.z, x1.z, az);
                aw = fmaf(w0.w, x0.w, aw); aw = fmaf(w1.w, x1.w, aw);

                if (q == 0) {                     // slot s0%3 consumed
                    __syncthreads();
                    if (tid == 0)
                        issue_tile(s0 + 3, ntiles, bid, w, smem_base, mbar_base);
                }
                if (q == 2) {                     // slots (s0+1,s0+2)%3 consumed
                    __syncthreads();
                    if (tid == 0) {
                        issue_tile(s0 + 4, ntiles, bid, w, smem_base, mbar_base);
                        issue_tile(s0 + 5, ntiles, bid, w, smem_base, mbar_base);
                    }
                }
            }
        }

        if (!doRead) break;           // write-only epilogue done

        // ---- Reduce (barrier also proves tile 3's slot consumed) ----
#pragma unroll
        for (int o = 16; o > 0; o >>= 1) {
            ax += __shfl_xor_sync(0xffffffffu, ax, o);
            ay += __shfl_xor_sync(0xffffffffu, ay, o);
            az += __shfl_xor_sync(0xffffffffu, az, o);
            aw += __shfl_xor_sync(0xffffffffu, aw, o);
        }
        if (lane == 0) red[warp] = make_float4(ax, ay, az, aw);
        __syncthreads();

        if (tid == 0)
            issue_tile(s0 + 6, ntiles, bid, w, smem_base, mbar_base);

        float4 t = red[lane];
        float Ix = t.x, Iy = t.y, Iz = t.z, Iw = t.w;
#pragma unroll
        for (int o = 16; o > 0; o >>= 1) {
            Ix += __shfl_xor_sync(0xffffffffu, Ix, o);
            Iy += __shfl_xor_sync(0xffffffffu, Iy, o);
            Iz += __shfl_xor_sync(0xffffffffu, Iz, o);
            Iw += __shfl_xor_sync(0xffffffffu, Iw, o);
        }

        // ---- Scalar neuron update; carry to next iteration ----
        const float S    = Ix - Iy + Iz - Iw;
        const float dv   = (S - vn) * 0.05f;            // DT/TAU_V
        const float th   = tanhf(vn);
        const float actd = (vn > 0.f) ? (1.f - th * th) : 0.f;

        if (tid == 0) {
            v_out[n] = vn + dv;
            r_out[n] = (vn > 0.f) ? th : 0.f;
        }

        Ixp = Ix; Iyp = Iy; Izp = Iz; Iwp = Iw;
        regp = rn * actd * dv * 0.02f;                  // / TAU_W
    }
}

extern "C" void kernel_launch(void* const* d_in, const int* in_sizes, int n_in,
                              void* d_out, int out_size)
{
    const float4* w = (const float4*)d_in[0];
    const float4* x = (const float4*)d_in[1];
    const float*  v = (const float*)d_in[2];
    const float*  r = (const float*)d_in[3];

    const int N = in_sizes[2];                 // 4096 neurons

    float*  out   = (float*)d_out;
    float*  v_out = out;
    float*  r_out = out + N;
    float4* w_out = (float4*)(out + 2 * (size_t)N);

    cudaFuncSetAttribute(dvbundle_pipe3,
                         cudaFuncAttributeMaxDynamicSharedMemorySize,
                         SMEM_B);

    dvbundle_pipe3<<<GRID, THREADS, SMEM_B>>>(w, x, v, r, v_out, r_out, w_out, N);
}

// round 13
// speedup vs baseline: 1.2890x; 1.0721x over previous
#include <cuda_runtime.h>
#include <cstdint>

// DVBundle: TMA-ring persistent kernel, R4 architecture with split
// (producer-only-blocking) named barriers for slot release.
//
// w [4096, 8192, 4] f32 = 8192 float4/row = 4 tiles x 32KB.
// x [8192,4] = 128KB cached in smem once. Output: [v|r|w_new].
// Grid = 148 persistent CTAs, 1024 threads, 3-slot ring (96KB).
//
// Pass 1, tiles 0..2: after FMA-consuming a slot, warps 1..31 do a
// non-blocking bar.arrive and run ahead; warp 0 does bar.sync on the same
// named barrier (ids 1..3) and tid0 then issues that slot's refill (s+3).
// Only the refiller pays the sync latency -- no 32-warp convoy.
// Tile 3's consumption is proven by the reduce __syncthreads (the only
// full barrier per iteration), after which tile s0+6 is issued.
// Pass 2 writes from the wv[8] register stash + smem x (phase-separated
// write burst -- the structure with the best sustained-bench behavior).

#define NI        8192
#define THREADS   1024
#define GRID      148
#define TILE_F4   2048               // 32KB tile = 2048 float4
#define TILE_B    32768
#define NBUF      3

#define OFF_X     0                              // 8192*16 = 131072
#define OFF_RING  131072                         // 3*32768 = 98304
#define OFF_RED   (OFF_RING + NBUF * TILE_B)     // 229376, 33*16 = 528
#define OFF_MBAR  (OFF_RED + 33 * 16)            // 229904
#define SMEM_B    (OFF_MBAR + NBUF * 8)          // 229928

__device__ __forceinline__ void mbar_wait_acq(uint32_t mbar, uint32_t parity)
{
    uint32_t done;
    asm volatile(
        "{\n\t.reg .pred p;\n\t"
        "mbarrier.try_wait.parity.acquire.cta.shared::cta.b64 p, [%1], %2;\n\t"
        "selp.b32 %0, 1, 0, p;\n\t}"
        : "=r"(done) : "r"(mbar), "r"(parity) : "memory");
    if (!done) {
        asm volatile(
            "{\n\t.reg .pred P1;\n\t"
            "WL_%=:\n\t"
            "mbarrier.try_wait.parity.acquire.cta.shared::cta.b64 P1, [%0], %1, 0x989680;\n\t"
            "@P1 bra.uni WD_%=;\n\t"
            "bra.uni WL_%=;\n\t"
            "WD_%=:\n\t}"
            :: "r"(mbar), "r"(parity) : "memory");
    }
}

// Issue TMA load of tile-stream index s into ring slot (s % 3).
__device__ __forceinline__ void issue_tile(int s, int ntiles, int bid,
                                           const float4* __restrict__ w,
                                           uint32_t smem_base, uint32_t mbar_base)
{
    if (s < ntiles) {
        const int      b  = s % NBUF;
        const uint32_t mb = mbar_base + 8u * b;
        asm volatile("mbarrier.arrive.expect_tx.shared.b64 _, [%0], %1;"
                     :: "r"(mb), "r"((uint32_t)TILE_B) : "memory");
        const void* src = (const void*)(w + (size_t)(bid + (s >> 2) * GRID) * NI
                                          + (size_t)(s & 3) * TILE_F4);
        asm volatile(
            "cp.async.bulk.shared::cluster.global.mbarrier::complete_tx::bytes "
            "[%0], [%1], %2, [%3];"
            :: "r"(smem_base + (uint32_t)OFF_RING + (uint32_t)(b * TILE_B)),
               "l"(src), "r"((uint32_t)TILE_B), "r"(mb) : "memory");
    }
}

__global__ __launch_bounds__(THREADS, 1)
void dvbundle_split(const float4* __restrict__ w,
                    const float4* __restrict__ x,
                    const float*  __restrict__ v,
                    const float*  __restrict__ r,
                    float*        __restrict__ v_out,
                    float*        __restrict__ r_out,
                    float4*       __restrict__ w_out,
                    int n_neurons)
{
    extern __shared__ char smem[];
    float4* xs   = (float4*)(smem + OFF_X);
    float4* ring = (float4*)(smem + OFF_RING);
    float4* red  = (float4*)(smem + OFF_RED);

    const int tid  = threadIdx.x;
    const int warp = tid >> 5;
    const int lane = tid & 31;
    const int bid  = blockIdx.x;

    const uint32_t smem_base = (uint32_t)__cvta_generic_to_shared(smem);
    const uint32_t mbar_base = smem_base + OFF_MBAR;

    // ---- Prologue: x -> smem, init mbars, prime the ring ----
#pragma unroll
    for (int j = 0; j < 8; ++j)
        xs[tid + j * THREADS] = x[tid + j * THREADS];

    if (tid == 0) {
#pragma unroll
        for (int b = 0; b < NBUF; ++b)
            asm volatile("mbarrier.init.shared.b64 [%0], %1;"
                         :: "r"(mbar_base + 8u * b), "r"(1u) : "memory");
    }
    __syncthreads();

    const int niters = (n_neurons - bid + GRID - 1) / GRID;
    const int ntiles = 4 * niters;

    if (tid == 0) {
        issue_tile(0, ntiles, bid, w, smem_base, mbar_base);
        issue_tile(1, ntiles, bid, w, smem_base, mbar_base);
        issue_tile(2, ntiles, bid, w, smem_base, mbar_base);
    }

    int n = bid;
    for (int it = 0; it < niters; ++it, n += GRID) {
        const float vn = v[n];
        const float rn = r[n];

        float4 wv[8];
        float ax = 0.f, ay = 0.f, az = 0.f, aw = 0.f;
        const int s0 = 4 * it;

        // ---- Pass 1: 4 tiles, LDS -> regs -> FMA; split-barrier release ----
#pragma unroll
        for (int q = 0; q < 4; ++q) {
            const int s = s0 + q;
            const int b = s % NBUF;
            mbar_wait_acq(mbar_base + 8u * b, (uint32_t)(s / NBUF) & 1u);

            const float4* wb = ring + b * TILE_F4;
            const float4 w0 = wb[tid];
            const float4 w1 = wb[tid + THREADS];
            const float4 x0 = xs[q * TILE_F4 + tid];
            const float4 x1 = xs[q * TILE_F4 + THREADS + tid];
            wv[2 * q]     = w0;
            wv[2 * q + 1] = w1;
            ax = fmaf(w0.x, x0.x, ax); ax = fmaf(w1.x, x1.x, ax);
            ay = fmaf(w0.y, x0.y, ay); ay = fmaf(w1.y, x1.y, ay);
            az = fmaf(w0.z, x0.z, az); az = fmaf(w1.z, x1.z, az);
            aw = fmaf(w0.w, x0.w, aw); aw = fmaf(w1.w, x1.w, aw);

            // Split slot-release barrier: the FMAs above consumed the LDS
            // data, so program order guarantees the slot read is complete
            // before the arrive. Warps 1..31 do not block.
            if (q < 3) {
                const int barid = 1 + b;               // named barriers 1..3
                if (warp == 0) {
                    asm volatile("bar.sync %0, %1;"
                                 :: "r"(barid), "r"(THREADS) : "memory");
                    if (tid == 0)
                        issue_tile(s + 3, ntiles, bid, w, smem_base, mbar_base);
                } else {
                    asm volatile("bar.arrive %0, %1;"
                                 :: "r"(barid), "r"(THREADS) : "memory");
                }
            }
        }

        // ---- Reduce: shfl -> partials -> THE full barrier -> refill ----
#pragma unroll
        for (int o = 16; o > 0; o >>= 1) {
            ax += __shfl_xor_sync(0xffffffffu, ax, o);
            ay += __shfl_xor_sync(0xffffffffu, ay, o);
            az += __shfl_xor_sync(0xffffffffu, az, o);
            aw += __shfl_xor_sync(0xffffffffu, aw, o);
        }
        if (lane == 0) red[warp] = make_float4(ax, ay, az, aw);
        __syncthreads();            // publishes partials; proves tile 3 consumed

        if (tid == 0)
            issue_tile(s0 + 6, ntiles, bid, w, smem_base, mbar_base);

        float4 t = red[lane];
        float Ix = t.x, Iy = t.y, Iz = t.z, Iw = t.w;
#pragma unroll
        for (int o = 16; o > 0; o >>= 1) {
            Ix += __shfl_xor_sync(0xffffffffu, Ix, o);
            Iy += __shfl_xor_sync(0xffffffffu, Iy, o);
            Iz += __shfl_xor_sync(0xffffffffu, Iz, o);
            Iw += __shfl_xor_sync(0xffffffffu, Iw, o);
        }

        // ---- Scalar neuron update ----
        const float S    = Ix - Iy + Iz - Iw;
        const float dv   = (S - vn) * 0.05f;            // DT/TAU_V
        const float th   = tanhf(vn);
        const float actd = (vn > 0.f) ? (1.f - th * th) : 0.f;
        const float reg  = rn * actd * dv * 0.02f;      // / TAU_W

        if (tid == 0) {
            v_out[n] = vn + dv;
            r_out[n] = (vn > 0.f) ? th : 0.f;
        }

        // ---- Pass 2: update from regs + smem x, direct STG ----
        float4* wdst = w_out + (size_t)n * NI;
#pragma unroll
        for (int q = 0; q < 4; ++q) {
#pragma unroll
            for (int h = 0; h < 2; ++h) {
                const int    idx = q * TILE_F4 + h * THREADS + tid;
                const float4 xv  = xs[idx];
                const float4 wj  = wv[2 * q + h];
                float4 o;
                o.x = fmaf(reg, fmaf(-wj.x, Ix, 0.5f * xv.x), wj.x);
                o.y = fmaf(reg, fmaf(-wj.y, Iy, 0.5f * xv.y), wj.y);
                o.z = fmaf(reg, fmaf(-wj.z, Iz, 0.5f * xv.z), wj.z);
                o.w = fmaf(reg, fmaf(-wj.w, Iw, 0.5f * xv.w), wj.w);
                wdst[idx] = o;
            }
        }
    }
}

extern "C" void kernel_launch(void* const* d_in, const int* in_sizes, int n_in,
                              void* d_out, int out_size)
{
    const float4* w = (const float4*)d_in[0];
    const float4* x = (const float4*)d_in[1];
    const float*  v = (const float*)d_in[2];
    const float*  r = (const float*)d_in[3];

    const int N = in_sizes[2];                 // 4096 neurons

    float*  out   = (float*)d_out;
    float*  v_out = out;
    float*  r_out = out + N;
    float4* w_out = (float4*)(out + 2 * (size_t)N);

    cudaFuncSetAttribute(dvbundle_split,
                         cudaFuncAttributeMaxDynamicSharedMemorySize,
                         SMEM_B);

    dvbundle_split<<<GRID, THREADS, SMEM_B>>>(w, x, v, r, v_out, r_out, w_out, N);
}